// round 13
// baseline (speedup 1.0000x reference)
#include <cuda_runtime.h>
#include <cuda_bf16.h>
#include <math.h>
#include <stdint.h>

#define MAXN 100000
#define MAXE 3200000
#define HD 64
#define SCAN_B 1024
#define MAXBLK 256   // ceil(MAXN/SCAN_B) = 98 <= 256

// ---------------- scratch (__device__ globals) ------------------------------------
__device__ int   g_cnt [MAXN];
__device__ int   g_rows[MAXN + 1];
__device__ int   g_curs[MAXN];
__device__ int   g_csr [MAXE];
__device__ int   g_bsum[MAXBLK];
__device__ int   g_boff[MAXBLK];
__device__ int   g_total;
__device__ float g_dinv[MAXN];
__device__ __align__(16) __nv_bfloat162 g_h [(size_t)MAXN * 32];  // layer-1 msgs
__device__ __align__(16) __nv_bfloat162 g_h2[(size_t)MAXN * 32];  // layer-2 msgs
__device__ int   g_is64;

__device__ __forceinline__ int edge_at(const char* ei, long long idx, int is64) {
    if (is64) return (int)(((const long long*)ei)[idx]);
    return ((const int*)ei)[idx];
}

// ---------------- zero / detect (split so k_hist is submission #4) ----------------
__global__ void k_zero(int n) {
    int i = blockIdx.x * blockDim.x + threadIdx.x;
    if (i < n) g_cnt[i] = 0;
}

__global__ void k_detect(const unsigned int* __restrict__ ei) {
    if (threadIdx.x == 0 && blockIdx.x == 0) {
        int all0 = 1;
        #pragma unroll 8
        for (int j = 0; j < 64; j++)
            if (ei[2 * j + 1] != 0u) all0 = 0;
        g_is64 = all0;
    }
}

__global__ void k_hist(const char* __restrict__ ei, int E) {
    int i = blockIdx.x * blockDim.x + threadIdx.x;
    if (i >= E) return;
    int d = edge_at(ei, (long long)E + i, g_is64);
    atomicAdd(&g_cnt[d], 1);
}

__global__ void k_dinv(int n) {
    int i = blockIdx.x * blockDim.x + threadIdx.x;
    if (i < n) g_dinv[i] = rsqrtf((float)g_cnt[i] + 1.0f);
}

// ---------------- device-wide exclusive scan (3 phases) ---------------------------
__global__ void __launch_bounds__(SCAN_B) k_scan1(int n) {
    __shared__ int wsum[32];
    const int tid  = threadIdx.x;
    const int lane = tid & 31;
    const int wid  = tid >> 5;
    const int i    = blockIdx.x * SCAN_B + tid;

    int v0 = (i < n) ? g_cnt[i] : 0;
    int v = v0;
    #pragma unroll
    for (int off = 1; off < 32; off <<= 1) {
        int t = __shfl_up_sync(0xffffffffu, v, off);
        if (lane >= off) v += t;
    }
    if (lane == 31) wsum[wid] = v;
    __syncthreads();
    if (wid == 0) {
        int t = wsum[lane];
        #pragma unroll
        for (int off = 1; off < 32; off <<= 1) {
            int u = __shfl_up_sync(0xffffffffu, t, off);
            if (lane >= off) t += u;
        }
        wsum[lane] = t;
    }
    __syncthreads();
    int woff = (wid > 0) ? wsum[wid - 1] : 0;
    if (i < n) g_rows[i] = woff + v - v0;
    if (tid == 0) g_bsum[blockIdx.x] = wsum[31];
}

__global__ void __launch_bounds__(256) k_scan2(int nb) {
    __shared__ int wsum[8];
    const int tid  = threadIdx.x;
    const int lane = tid & 31;
    const int wid  = tid >> 5;

    int v0 = (tid < nb) ? g_bsum[tid] : 0;
    int v = v0;
    #pragma unroll
    for (int off = 1; off < 32; off <<= 1) {
        int t = __shfl_up_sync(0xffffffffu, v, off);
        if (lane >= off) v += t;
    }
    if (lane == 31) wsum[wid] = v;
    __syncthreads();
    if (wid == 0 && lane < 8) {
        int t = wsum[lane];
        #pragma unroll
        for (int off = 1; off < 8; off <<= 1) {
            int u = __shfl_up_sync(0xffu, t, off);
            if (lane >= off) t += u;
        }
        wsum[lane] = t;
    }
    __syncthreads();
    int woff = (wid > 0) ? wsum[wid - 1] : 0;
    if (tid < nb) g_boff[tid] = woff + v - v0;
    if (tid == 0) g_total = wsum[7];
}

__global__ void __launch_bounds__(SCAN_B) k_scan3(int n) {
    const int i = blockIdx.x * SCAN_B + threadIdx.x;
    if (i < n) {
        int r = g_rows[i] + g_boff[blockIdx.x];
        g_rows[i] = r;
        g_curs[i] = r;
    }
    if (i == 0) g_rows[n] = g_total;
}

__global__ void k_fill(const char* __restrict__ ei, int E) {
    int i = blockIdx.x * blockDim.x + threadIdx.x;
    if (i >= E) return;
    int is64 = g_is64;
    int s = edge_at(ei, i, is64);
    int d = edge_at(ei, (long long)E + i, is64);
    int pos = atomicAdd(&g_curs[d], 1);
    g_csr[pos] = s;
}

// ---------------- GEMM1 (X @ W1) -> bf16 h (unscaled), 8x4 register tiling --------
__global__ void __launch_bounds__(256)
k_gemm1(const float* __restrict__ A, const float* __restrict__ W,
        __nv_bfloat162* __restrict__ hout, int n)
{
    __shared__ float As[128][64];   // 32 KB
    __shared__ float Ws[64][64];    // 16 KB

    const int tid = threadIdx.x;
    const int r0  = blockIdx.x * 128;
    const int tc  = tid & 15;
    const int tr  = tid >> 4;

    float acc[8][4];
    #pragma unroll
    for (int i = 0; i < 8; i++)
        #pragma unroll
        for (int j = 0; j < 4; j++) acc[i][j] = 0.f;

    for (int kt = 0; kt < 128; kt += 64) {
        __syncthreads();
        for (int i = tid; i < 1024; i += 256)
            reinterpret_cast<float4*>(&Ws[0][0])[i] =
                reinterpret_cast<const float4*>(W + kt * 64)[i];
        for (int i = tid; i < 128 * 16; i += 256) {
            int rr = i >> 4, cc = i & 15;
            int row = r0 + rr;
            float4 v = make_float4(0.f, 0.f, 0.f, 0.f);
            if (row < n)
                v = __ldg(reinterpret_cast<const float4*>(A + (size_t)row * 128 + kt) + cc);
            *reinterpret_cast<float4*>(&As[rr][cc << 2]) = v;
        }
        __syncthreads();

        #pragma unroll 4
        for (int k4 = 0; k4 < 64; k4 += 4) {
            float4 a[8];
            #pragma unroll
            for (int i = 0; i < 8; i++)
                a[i] = *reinterpret_cast<const float4*>(&As[8 * tr + i][k4]);
            float4 w0 = *reinterpret_cast<const float4*>(&Ws[k4 + 0][tc << 2]);
            float4 w1 = *reinterpret_cast<const float4*>(&Ws[k4 + 1][tc << 2]);
            float4 w2 = *reinterpret_cast<const float4*>(&Ws[k4 + 2][tc << 2]);
            float4 w3 = *reinterpret_cast<const float4*>(&Ws[k4 + 3][tc << 2]);
            #pragma unroll
            for (int i = 0; i < 8; i++) {
                float4 ai = a[i];
                acc[i][0] = fmaf(ai.x, w0.x, acc[i][0]);
                acc[i][0] = fmaf(ai.y, w1.x, acc[i][0]);
                acc[i][0] = fmaf(ai.z, w2.x, acc[i][0]);
                acc[i][0] = fmaf(ai.w, w3.x, acc[i][0]);
                acc[i][1] = fmaf(ai.x, w0.y, acc[i][1]);
                acc[i][1] = fmaf(ai.y, w1.y, acc[i][1]);
                acc[i][1] = fmaf(ai.z, w2.y, acc[i][1]);
                acc[i][1] = fmaf(ai.w, w3.y, acc[i][1]);
                acc[i][2] = fmaf(ai.x, w0.z, acc[i][2]);
                acc[i][2] = fmaf(ai.y, w1.z, acc[i][2]);
                acc[i][2] = fmaf(ai.z, w2.z, acc[i][2]);
                acc[i][2] = fmaf(ai.w, w3.z, acc[i][2]);
                acc[i][3] = fmaf(ai.x, w0.w, acc[i][3]);
                acc[i][3] = fmaf(ai.y, w1.w, acc[i][3]);
                acc[i][3] = fmaf(ai.z, w2.w, acc[i][3]);
                acc[i][3] = fmaf(ai.w, w3.w, acc[i][3]);
            }
        }
    }

    #pragma unroll
    for (int i = 0; i < 8; i++) {
        int row = r0 + 8 * tr + i;
        if (row < n) {
            __nv_bfloat162 p0 = __floats2bfloat162_rn(acc[i][0], acc[i][1]);
            __nv_bfloat162 p1 = __floats2bfloat162_rn(acc[i][2], acc[i][3]);
            uint2 v;
            v.x = *reinterpret_cast<unsigned int*>(&p0);
            v.y = *reinterpret_cast<unsigned int*>(&p1);
            *reinterpret_cast<uint2*>(hout + (size_t)row * 32 + (tc << 1)) = v;
        }
    }
}

// ---------------- scale pass for layer-1 h (h *= dinv[row]) -----------------------
__global__ void k_scale(__nv_bfloat162* __restrict__ h, int n) {
    long long i = (long long)blockIdx.x * blockDim.x + threadIdx.x;
    if (i >= (long long)n * 32) return;
    float di = g_dinv[(int)(i >> 5)];
    float2 v = __bfloat1622float2(h[i]);
    h[i] = __floats2bfloat162_rn(di * v.x, di * v.y);
}

// ---------------- quarter-warp CSR gather: 4 edges/iter, uint4 loads --------------
// lane = q*8 + l8: quarter q handles edges j==q (mod 4); lane owns 8 features
// (one uint4 = 4 bf162). Unified predicated chunk loop + next-chunk index prefetch.
// After xor-combine(8,16), every lane holds the full sum for its l8 feature group.
__device__ __forceinline__ void gather_row4(const __nv_bfloat162* __restrict__ h,
                                            int node, int lane, float* acc)
{
    const int q  = lane >> 3;
    const int l8 = lane & 7;
    const int start = g_rows[node];
    const int end   = g_rows[node + 1];

    // self loop: quarter 0 only (others contribute zero)
    {
        uint4 rv = make_uint4(0u, 0u, 0u, 0u);
        if (q == 0)
            rv = __ldg(reinterpret_cast<const uint4*>(h + (size_t)node * 32) + l8);
        float2 a = __bfloat1622float2(*reinterpret_cast<__nv_bfloat162*>(&rv.x));
        float2 b = __bfloat1622float2(*reinterpret_cast<__nv_bfloat162*>(&rv.y));
        float2 c = __bfloat1622float2(*reinterpret_cast<__nv_bfloat162*>(&rv.z));
        float2 d = __bfloat1622float2(*reinterpret_cast<__nv_bfloat162*>(&rv.w));
        acc[0] = a.x; acc[1] = a.y; acc[2] = b.x; acc[3] = b.y;
        acc[4] = c.x; acc[5] = c.y; acc[6] = d.x; acc[7] = d.y;
    }

    const int total = end - start;
    const int nch = (total + 31) >> 5;
    int s = 0;
    if (lane < total) s = __ldg(g_csr + start + lane);

    for (int c = 0; c < nch; c++) {
        const int ebase = start + (c << 5);
        int cnt = end - ebase; if (cnt > 32) cnt = 32;
        // prefetch next chunk's indices
        int s_next = 0;
        int rem_next = end - (ebase + 32);
        if (lane < rem_next) s_next = __ldg(g_csr + ebase + 32 + lane);

        #pragma unroll
        for (int k = 0; k < 8; k++) {
            int j = (k << 2) + q;
            int sj = __shfl_sync(0xffffffffu, s, j);
            uint4 rv = make_uint4(0u, 0u, 0u, 0u);
            if (j < cnt)
                rv = __ldg(reinterpret_cast<const uint4*>(h + (size_t)sj * 32) + l8);
            float2 a = __bfloat1622float2(*reinterpret_cast<__nv_bfloat162*>(&rv.x));
            float2 b = __bfloat1622float2(*reinterpret_cast<__nv_bfloat162*>(&rv.y));
            float2 cc = __bfloat1622float2(*reinterpret_cast<__nv_bfloat162*>(&rv.z));
            float2 d = __bfloat1622float2(*reinterpret_cast<__nv_bfloat162*>(&rv.w));
            acc[0] += a.x;  acc[1] += a.y;  acc[2] += b.x;  acc[3] += b.y;
            acc[4] += cc.x; acc[5] += cc.y; acc[6] += d.x;  acc[7] += d.y;
        }
        s = s_next;
    }

    #pragma unroll
    for (int i = 0; i < 8; i++) {
        acc[i] += __shfl_xor_sync(0xffffffffu, acc[i], 8);
        acc[i] += __shfl_xor_sync(0xffffffffu, acc[i], 16);
    }
}

// ---------------- fused: gather1 + b1 + relu + (@W2) + dinv-scale -> bf16 h2 ------
__global__ void __launch_bounds__(256, 4)
k_gather_gemm(const __nv_bfloat162* __restrict__ h, const float* __restrict__ b1,
              const float* __restrict__ W2, __nv_bfloat162* __restrict__ h2, int n)
{
    __shared__ float W2s[64 * 64];                 // 16 KB
    __shared__ __align__(16) float hs[8][68];
    __shared__ __align__(16) float b1s[64];

    const int tid  = threadIdx.x;
    const int warp = tid >> 5;
    const int lane = tid & 31;

    for (int i = tid; i < 64 * 64 / 4; i += 256)
        reinterpret_cast<float4*>(W2s)[i] = reinterpret_cast<const float4*>(W2)[i];
    if (tid < 64) b1s[tid] = b1[tid];
    __syncthreads();

    const float2* W2s2 = reinterpret_cast<const float2*>(W2s);

    int node0 = (blockIdx.x * 8 + warp) * 4;
    #pragma unroll 1
    for (int nd = 0; nd < 4; nd++) {
        int node = node0 + nd;
        if (node >= n) return;

        float acc[8];
        gather_row4(h, node, lane, acc);
        float di = g_dinv[node];
        if (lane < 8) {
            #pragma unroll
            for (int i = 0; i < 8; i++)
                hs[warp][(lane << 3) + i] =
                    fmaxf(b1s[(lane << 3) + i] + di * acc[i], 0.f);
        }
        __syncwarp();

        // matvec: out[2*lane, 2*lane+1] = relu(agg) @ W2
        float2 o = make_float2(0.f, 0.f);
        const float* hrow = hs[warp];
        #pragma unroll 16
        for (int k = 0; k < 64; k++) {
            float hk = hrow[k];
            float2 w = W2s2[(k << 5) + lane];
            o.x = fmaf(hk, w.x, o.x);
            o.y = fmaf(hk, w.y, o.y);
        }
        __syncwarp();
        h2[(size_t)node * 32 + lane] = __floats2bfloat162_rn(di * o.x, di * o.y);
    }
}

// ---------------- fused: gather2 + b2 + relu + (@Wf + bf) + log_softmax -> out ----
__global__ void __launch_bounds__(256, 4)
k_gather_final(const __nv_bfloat162* __restrict__ h, const float* __restrict__ b2,
               const float* __restrict__ Wf, const float* __restrict__ bf,
               float* __restrict__ out, int n)
{
    __shared__ float Wfs[64 * 40];                 // 10 KB
    __shared__ __align__(16) float hs[8][68];
    __shared__ __align__(16) float b2s[64];
    __shared__ float bfs[40];

    const int tid  = threadIdx.x;
    const int warp = tid >> 5;
    const int lane = tid & 31;

    for (int i = tid; i < 64 * 40; i += 256) Wfs[i] = Wf[i];
    if (tid < 64) b2s[tid] = b2[tid];
    if (tid < 40) bfs[tid] = bf[tid];
    __syncthreads();

    int node0 = (blockIdx.x * 8 + warp) * 4;
    #pragma unroll 1
    for (int nd = 0; nd < 4; nd++) {
        int node = node0 + nd;
        if (node >= n) return;

        float acc[8];
        gather_row4(h, node, lane, acc);
        float di = g_dinv[node];
        if (lane < 8) {
            #pragma unroll
            for (int i = 0; i < 8; i++)
                hs[warp][(lane << 3) + i] =
                    fmaxf(b2s[(lane << 3) + i] + di * acc[i], 0.f);
        }
        __syncwarp();

        float a0 = 0.f, a1 = 0.f;
        if (lane < 20) {
            const float* hrow = hs[warp];
            #pragma unroll 8
            for (int k = 0; k < 64; k++) {
                float hk = hrow[k];
                a0 = fmaf(hk, Wfs[k * 40 + lane],      a0);
                a1 = fmaf(hk, Wfs[k * 40 + lane + 20], a1);
            }
            a0 += bfs[lane];
            a1 += bfs[lane + 20];
        }

        float m = (lane < 20) ? fmaxf(a0, a1) : -INFINITY;
        #pragma unroll
        for (int o = 16; o; o >>= 1) m = fmaxf(m, __shfl_xor_sync(0xffffffffu, m, o));
        float ssum = (lane < 20) ? (expf(a0 - m) + expf(a1 - m)) : 0.f;
        #pragma unroll
        for (int o = 16; o; o >>= 1) ssum += __shfl_xor_sync(0xffffffffu, ssum, o);
        float lse = m + logf(ssum);

        if (lane < 20) {
            out[(size_t)node * 40 + lane]      = a0 - lse;
            out[(size_t)node * 40 + lane + 20] = a1 - lse;
        }
        __syncwarp();
    }
}

// ---------------- launch ----------------------------------------------------------
static cudaStream_t get_aux_stream() {
    static cudaStream_t s = [] {
        cudaStream_t t;
        cudaStreamCreateWithFlags(&t, cudaStreamNonBlocking);
        return t;
    }();
    return s;
}
static cudaEvent_t make_event() {
    cudaEvent_t e;
    cudaEventCreateWithFlags(&e, cudaEventDisableTiming);
    return e;
}
static cudaEvent_t get_ev_root() { static cudaEvent_t e = make_event(); return e; }
static cudaEvent_t get_ev_dinv() { static cudaEvent_t e = make_event(); return e; }
static cudaEvent_t get_ev_csr()  { static cudaEvent_t e = make_event(); return e; }

extern "C" void kernel_launch(void* const* d_in, const int* in_sizes, int n_in,
                              void* d_out, int out_size)
{
    const float* x  = (const float*)d_in[0];
    const char*  ei = (const char*) d_in[1];
    const float* W1 = (const float*)d_in[2];
    const float* b1 = (const float*)d_in[3];
    const float* W2 = (const float*)d_in[4];
    const float* b2 = (const float*)d_in[5];
    const float* Wf = (const float*)d_in[6];
    const float* bf = (const float*)d_in[7];
    float* out = (float*)d_out;

    const int n = in_sizes[0] / 128;
    const int E = in_sizes[1] / 2;

    __nv_bfloat162 *hbuf, *h2buf;
    cudaGetSymbolAddress((void**)&hbuf,  g_h);
    cudaGetSymbolAddress((void**)&h2buf, g_h2);

    const int nb256   = (n + 255) / 256;
    const int eb256   = (E + 255) / 256;
    const int gemmb   = (n + 127) / 128;
    const int fuseb   = (n + 31) / 32;
    const int scanb   = (n + SCAN_B - 1) / SCAN_B;
    const int scaleb  = (n * 32 + 255) / 256;

    cudaStream_t aux = get_aux_stream();
    cudaEvent_t evRoot = get_ev_root();
    cudaEvent_t evDinv = get_ev_dinv();
    cudaEvent_t evCSR  = get_ev_csr();

    // fork aux stream off the captured (default) stream
    cudaEventRecord(evRoot, 0);
    cudaStreamWaitEvent(aux, evRoot, 0);

    // submission order: gemm1 first (no deps), then CSR chain; k_hist lands in
    // profiler slot 4 so next round prices the CSR front.
    k_gemm1<<<gemmb, 256>>>(x, W1, hbuf, n);                             // 1 (main)
    k_zero<<<nb256, 256, 0, aux>>>(n);                                   // 2
    k_detect<<<1, 32, 0, aux>>>((const unsigned int*)ei);                // 3
    k_hist<<<eb256, 256, 0, aux>>>(ei, E);                               // 4
    k_dinv<<<nb256, 256, 0, aux>>>(n);                                   // 5
    cudaEventRecord(evDinv, aux);
    k_scan1<<<scanb, SCAN_B, 0, aux>>>(n);
    k_scan2<<<1, 256, 0, aux>>>(scanb);
    k_scan3<<<scanb, SCAN_B, 0, aux>>>(n);
    k_fill<<<eb256, 256, 0, aux>>>(ei, E);
    cudaEventRecord(evCSR, aux);

    // main: scale after dinv; gathers after CSR
    cudaStreamWaitEvent(0, evDinv, 0);
    k_scale<<<scaleb, 256>>>(hbuf, n);
    cudaStreamWaitEvent(0, evCSR, 0);

    k_gather_gemm<<<fuseb, 256>>>(hbuf, b1, W2, h2buf, n);
    k_gather_final<<<fuseb, 256>>>(h2buf, b2, Wf, bf, out, n);
}

// round 14
// speedup vs baseline: 1.0540x; 1.0540x over previous
#include <cuda_runtime.h>
#include <cuda_bf16.h>
#include <math.h>
#include <stdint.h>

#define MAXN 100000
#define MAXE 3200000
#define HD 64
#define SCAN_B 1024
#define MAXBLK 256   // ceil(MAXN/SCAN_B) = 98 <= 256

// ---------------- scratch (__device__ globals) ------------------------------------
__device__ int   g_cnt [MAXN];
__device__ int   g_rows[MAXN + 1];
__device__ int   g_curs[MAXN];
__device__ int   g_csr [MAXE];
__device__ int   g_bsum[MAXBLK];
__device__ float g_dinv[MAXN];
__device__ __align__(16) __nv_bfloat162 g_h [(size_t)MAXN * 32];  // layer-1 msgs
__device__ __align__(16) __nv_bfloat162 g_h2[(size_t)MAXN * 32];  // layer-2 msgs
__device__ int   g_is64;

__device__ __forceinline__ int edge_at(const char* ei, long long idx, int is64) {
    if (is64) return (int)(((const long long*)ei)[idx]);
    return ((const int*)ei)[idx];
}

// ---------------- dtype detect ----------------------------------------------------
__global__ void k_detect(const unsigned int* __restrict__ ei) {
    if (threadIdx.x == 0 && blockIdx.x == 0) {
        int all0 = 1;
        #pragma unroll 8
        for (int j = 0; j < 64; j++)
            if (ei[2 * j + 1] != 0u) all0 = 0;
        g_is64 = all0;
    }
}

// ---------------- histogram: 2 edges per thread -----------------------------------
__global__ void k_hist(const char* __restrict__ ei, int E) {
    int t = blockIdx.x * blockDim.x + threadIdx.x;
    long long e0 = (long long)t * 2;
    if (e0 >= E) return;
    int is64 = g_is64;
    int d0 = edge_at(ei, (long long)E + e0, is64);
    atomicAdd(&g_cnt[d0], 1);
    if (e0 + 1 < E) {
        int d1 = edge_at(ei, (long long)E + e0 + 1, is64);
        atomicAdd(&g_cnt[d1], 1);
    }
}

// ---------------- scan phase 1 (+ dinv fused) -------------------------------------
__global__ void __launch_bounds__(SCAN_B) k_scan1(int n) {
    __shared__ int wsum[32];
    const int tid  = threadIdx.x;
    const int lane = tid & 31;
    const int wid  = tid >> 5;
    const int i    = blockIdx.x * SCAN_B + tid;

    int v0 = (i < n) ? g_cnt[i] : 0;
    int v = v0;
    #pragma unroll
    for (int off = 1; off < 32; off <<= 1) {
        int t = __shfl_up_sync(0xffffffffu, v, off);
        if (lane >= off) v += t;
    }
    if (lane == 31) wsum[wid] = v;
    __syncthreads();
    if (wid == 0) {
        int t = wsum[lane];
        #pragma unroll
        for (int off = 1; off < 32; off <<= 1) {
            int u = __shfl_up_sync(0xffffffffu, t, off);
            if (lane >= off) t += u;
        }
        wsum[lane] = t;
    }
    __syncthreads();
    int woff = (wid > 0) ? wsum[wid - 1] : 0;
    if (i < n) {
        g_rows[i] = woff + v - v0;                 // exclusive within block
        g_dinv[i] = rsqrtf((float)v0 + 1.0f);      // fused dinv
    }
    if (tid == 0) g_bsum[blockIdx.x] = wsum[31];
}

// ---------------- scan finalize: per-block redundant reduce of bsum ---------------
// Each block computes off = sum(bsum[0..bid-1]) with one warp, adds it, writes curs.
__global__ void __launch_bounds__(SCAN_B) k_scanfin(int n, int nb) {
    __shared__ int s_off, s_tot;
    const int tid = threadIdx.x;
    if (tid < 32) {
        int accOff = 0, accTot = 0;
        for (int t = tid; t < nb; t += 32) {
            int v = g_bsum[t];
            accTot += v;
            if (t < (int)blockIdx.x) accOff += v;
        }
        #pragma unroll
        for (int o = 16; o; o >>= 1) {
            accOff += __shfl_xor_sync(0xffffffffu, accOff, o);
            accTot += __shfl_xor_sync(0xffffffffu, accTot, o);
        }
        if (tid == 0) { s_off = accOff; s_tot = accTot; }
    }
    __syncthreads();
    const int i = blockIdx.x * SCAN_B + tid;
    if (i < n) {
        int r = g_rows[i] + s_off;
        g_rows[i] = r;
        g_curs[i] = r;
    }
    if (blockIdx.x == 0 && tid == 0) g_rows[n] = s_tot;
}

// ---------------- fill: 2 edges per thread ----------------------------------------
__global__ void k_fill(const char* __restrict__ ei, int E) {
    int t = blockIdx.x * blockDim.x + threadIdx.x;
    long long e0 = (long long)t * 2;
    if (e0 >= E) return;
    int is64 = g_is64;
    int s0 = edge_at(ei, e0, is64);
    int d0 = edge_at(ei, (long long)E + e0, is64);
    int p0 = atomicAdd(&g_curs[d0], 1);
    g_csr[p0] = s0;
    if (e0 + 1 < E) {
        int s1 = edge_at(ei, e0 + 1, is64);
        int d1 = edge_at(ei, (long long)E + e0 + 1, is64);
        int p1 = atomicAdd(&g_curs[d1], 1);
        g_csr[p1] = s1;
    }
}

// ---------------- GEMM1 (X @ W1) -> bf16 h (unscaled), 8x4 register tiling --------
__global__ void __launch_bounds__(256)
k_gemm1(const float* __restrict__ A, const float* __restrict__ W,
        __nv_bfloat162* __restrict__ hout, int n)
{
    __shared__ float As[128][64];   // 32 KB
    __shared__ float Ws[64][64];    // 16 KB

    const int tid = threadIdx.x;
    const int r0  = blockIdx.x * 128;
    const int tc  = tid & 15;
    const int tr  = tid >> 4;

    float acc[8][4];
    #pragma unroll
    for (int i = 0; i < 8; i++)
        #pragma unroll
        for (int j = 0; j < 4; j++) acc[i][j] = 0.f;

    for (int kt = 0; kt < 128; kt += 64) {
        __syncthreads();
        for (int i = tid; i < 1024; i += 256)
            reinterpret_cast<float4*>(&Ws[0][0])[i] =
                reinterpret_cast<const float4*>(W + kt * 64)[i];
        for (int i = tid; i < 128 * 16; i += 256) {
            int rr = i >> 4, cc = i & 15;
            int row = r0 + rr;
            float4 v = make_float4(0.f, 0.f, 0.f, 0.f);
            if (row < n)
                v = __ldg(reinterpret_cast<const float4*>(A + (size_t)row * 128 + kt) + cc);
            *reinterpret_cast<float4*>(&As[rr][cc << 2]) = v;
        }
        __syncthreads();

        #pragma unroll 4
        for (int k4 = 0; k4 < 64; k4 += 4) {
            float4 a[8];
            #pragma unroll
            for (int i = 0; i < 8; i++)
                a[i] = *reinterpret_cast<const float4*>(&As[8 * tr + i][k4]);
            float4 w0 = *reinterpret_cast<const float4*>(&Ws[k4 + 0][tc << 2]);
            float4 w1 = *reinterpret_cast<const float4*>(&Ws[k4 + 1][tc << 2]);
            float4 w2 = *reinterpret_cast<const float4*>(&Ws[k4 + 2][tc << 2]);
            float4 w3 = *reinterpret_cast<const float4*>(&Ws[k4 + 3][tc << 2]);
            #pragma unroll
            for (int i = 0; i < 8; i++) {
                float4 ai = a[i];
                acc[i][0] = fmaf(ai.x, w0.x, acc[i][0]);
                acc[i][0] = fmaf(ai.y, w1.x, acc[i][0]);
                acc[i][0] = fmaf(ai.z, w2.x, acc[i][0]);
                acc[i][0] = fmaf(ai.w, w3.x, acc[i][0]);
                acc[i][1] = fmaf(ai.x, w0.y, acc[i][1]);
                acc[i][1] = fmaf(ai.y, w1.y, acc[i][1]);
                acc[i][1] = fmaf(ai.z, w2.y, acc[i][1]);
                acc[i][1] = fmaf(ai.w, w3.y, acc[i][1]);
                acc[i][2] = fmaf(ai.x, w0.z, acc[i][2]);
                acc[i][2] = fmaf(ai.y, w1.z, acc[i][2]);
                acc[i][2] = fmaf(ai.z, w2.z, acc[i][2]);
                acc[i][2] = fmaf(ai.w, w3.z, acc[i][2]);
                acc[i][3] = fmaf(ai.x, w0.w, acc[i][3]);
                acc[i][3] = fmaf(ai.y, w1.w, acc[i][3]);
                acc[i][3] = fmaf(ai.z, w2.w, acc[i][3]);
                acc[i][3] = fmaf(ai.w, w3.w, acc[i][3]);
            }
        }
    }

    #pragma unroll
    for (int i = 0; i < 8; i++) {
        int row = r0 + 8 * tr + i;
        if (row < n) {
            __nv_bfloat162 p0 = __floats2bfloat162_rn(acc[i][0], acc[i][1]);
            __nv_bfloat162 p1 = __floats2bfloat162_rn(acc[i][2], acc[i][3]);
            uint2 v;
            v.x = *reinterpret_cast<unsigned int*>(&p0);
            v.y = *reinterpret_cast<unsigned int*>(&p1);
            *reinterpret_cast<uint2*>(hout + (size_t)row * 32 + (tc << 1)) = v;
        }
    }
}

// ---------------- scale pass for layer-1 h (h *= dinv[row]) -----------------------
__global__ void k_scale(__nv_bfloat162* __restrict__ h, int n) {
    long long i = (long long)blockIdx.x * blockDim.x + threadIdx.x;
    if (i >= (long long)n * 32) return;
    float di = g_dinv[(int)(i >> 5)];
    float2 v = __bfloat1622float2(h[i]);
    h[i] = __floats2bfloat162_rn(di * v.x, di * v.y);
}

// ---------------- warp CSR gather, 2 edges/iteration via half-warps (R10 ver) -----
__device__ __forceinline__ float4 gather_row2(const __nv_bfloat162* __restrict__ h,
                                              int node, int lane)
{
    const int half = lane >> 4;
    const int l16  = lane & 15;
    const int start = g_rows[node];
    const int end   = g_rows[node + 1];

    float4 acc;
    {   // self loop: only half 0 contributes (half 1 adds zeros)
        uint2 rv = make_uint2(0u, 0u);
        if (half == 0)
            rv = __ldg(reinterpret_cast<const uint2*>(h + (size_t)node * 32) + l16);
        float2 a = __bfloat1622float2(*reinterpret_cast<__nv_bfloat162*>(&rv.x));
        float2 b = __bfloat1622float2(*reinterpret_cast<__nv_bfloat162*>(&rv.y));
        acc = make_float4(a.x, a.y, b.x, b.y);
    }

    int e = start;
    for (; e + 32 <= end; e += 32) {
        int s = g_csr[e + lane];
        #pragma unroll
        for (int k = 0; k < 16; k++) {
            int sj = __shfl_sync(0xffffffffu, s, 2 * k + half);
            uint2 rv = __ldg(reinterpret_cast<const uint2*>(h + (size_t)sj * 32) + l16);
            float2 a = __bfloat1622float2(*reinterpret_cast<__nv_bfloat162*>(&rv.x));
            float2 b = __bfloat1622float2(*reinterpret_cast<__nv_bfloat162*>(&rv.y));
            acc.x += a.x; acc.y += a.y; acc.z += b.x; acc.w += b.y;
        }
    }
    int cnt = end - e;
    if (cnt > 0) {
        int s = (lane < cnt) ? g_csr[e + lane] : 0;
        for (int k2 = 0; k2 < cnt; k2 += 2) {
            int j = k2 + half;
            int sj = __shfl_sync(0xffffffffu, s, (j < cnt) ? j : 0);
            uint2 rv = make_uint2(0u, 0u);
            if (j < cnt)
                rv = __ldg(reinterpret_cast<const uint2*>(h + (size_t)sj * 32) + l16);
            float2 a = __bfloat1622float2(*reinterpret_cast<__nv_bfloat162*>(&rv.x));
            float2 b = __bfloat1622float2(*reinterpret_cast<__nv_bfloat162*>(&rv.y));
            acc.x += a.x; acc.y += a.y; acc.z += b.x; acc.w += b.y;
        }
    }
    // combine half-warps
    acc.x += __shfl_xor_sync(0xffffffffu, acc.x, 16);
    acc.y += __shfl_xor_sync(0xffffffffu, acc.y, 16);
    acc.z += __shfl_xor_sync(0xffffffffu, acc.z, 16);
    acc.w += __shfl_xor_sync(0xffffffffu, acc.w, 16);
    return acc;
}

// ---------------- fused: gather1 + b1 + relu + (@W2) + dinv-scale -> bf16 h2 ------
__global__ void __launch_bounds__(256)
k_gather_gemm(const __nv_bfloat162* __restrict__ h, const float* __restrict__ b1,
              const float* __restrict__ W2, __nv_bfloat162* __restrict__ h2, int n)
{
    __shared__ float W2s[64 * 64];                 // 16 KB
    __shared__ __align__(16) float hs[8][68];
    __shared__ __align__(16) float b1s[64];

    const int tid  = threadIdx.x;
    const int warp = tid >> 5;
    const int lane = tid & 31;

    for (int i = tid; i < 64 * 64 / 4; i += 256)
        reinterpret_cast<float4*>(W2s)[i] = reinterpret_cast<const float4*>(W2)[i];
    if (tid < 64) b1s[tid] = b1[tid];
    __syncthreads();

    const float2* W2s2 = reinterpret_cast<const float2*>(W2s);

    int node0 = (blockIdx.x * 8 + warp) * 4;
    #pragma unroll 1
    for (int nd = 0; nd < 4; nd++) {
        int node = node0 + nd;
        if (node >= n) return;

        float4 acc = gather_row2(h, node, lane);
        float di = g_dinv[node];
        if (lane < 16) {
            float4 bb = *reinterpret_cast<const float4*>(&b1s[lane << 2]);
            float4 hr = make_float4(fmaxf(bb.x + di * acc.x, 0.f),
                                    fmaxf(bb.y + di * acc.y, 0.f),
                                    fmaxf(bb.z + di * acc.z, 0.f),
                                    fmaxf(bb.w + di * acc.w, 0.f));
            *reinterpret_cast<float4*>(&hs[warp][lane << 2]) = hr;
        }
        __syncwarp();

        // matvec: out[2*lane, 2*lane+1] = relu(agg) @ W2
        float2 o = make_float2(0.f, 0.f);
        const float* hrow = hs[warp];
        #pragma unroll 16
        for (int k = 0; k < 64; k++) {
            float hk = hrow[k];
            float2 w = W2s2[(k << 5) + lane];
            o.x = fmaf(hk, w.x, o.x);
            o.y = fmaf(hk, w.y, o.y);
        }
        __syncwarp();
        h2[(size_t)node * 32 + lane] = __floats2bfloat162_rn(di * o.x, di * o.y);
    }
}

// ---------------- fused: gather2 + b2 + relu + (@Wf + bf) + log_softmax -> out ----
__global__ void __launch_bounds__(256)
k_gather_final(const __nv_bfloat162* __restrict__ h, const float* __restrict__ b2,
               const float* __restrict__ Wf, const float* __restrict__ bf,
               float* __restrict__ out, int n)
{
    __shared__ float Wfs[64 * 40];                 // 10 KB
    __shared__ __align__(16) float hs[8][68];
    __shared__ __align__(16) float b2s[64];
    __shared__ float bfs[40];

    const int tid  = threadIdx.x;
    const int warp = tid >> 5;
    const int lane = tid & 31;

    for (int i = tid; i < 64 * 40; i += 256) Wfs[i] = Wf[i];
    if (tid < 64) b2s[tid] = b2[tid];
    if (tid < 40) bfs[tid] = bf[tid];
    __syncthreads();

    int node0 = (blockIdx.x * 8 + warp) * 4;
    #pragma unroll 1
    for (int nd = 0; nd < 4; nd++) {
        int node = node0 + nd;
        if (node >= n) return;

        float4 acc = gather_row2(h, node, lane);
        float di = g_dinv[node];
        if (lane < 16) {
            float4 bb = *reinterpret_cast<const float4*>(&b2s[lane << 2]);
            float4 hr = make_float4(fmaxf(bb.x + di * acc.x, 0.f),
                                    fmaxf(bb.y + di * acc.y, 0.f),
                                    fmaxf(bb.z + di * acc.z, 0.f),
                                    fmaxf(bb.w + di * acc.w, 0.f));
            *reinterpret_cast<float4*>(&hs[warp][lane << 2]) = hr;
        }
        __syncwarp();

        float a0 = 0.f, a1 = 0.f;
        if (lane < 20) {
            const float* hrow = hs[warp];
            #pragma unroll 8
            for (int k = 0; k < 64; k++) {
                float hk = hrow[k];
                a0 = fmaf(hk, Wfs[k * 40 + lane],      a0);
                a1 = fmaf(hk, Wfs[k * 40 + lane + 20], a1);
            }
            a0 += bfs[lane];
            a1 += bfs[lane + 20];
        }

        float m = (lane < 20) ? fmaxf(a0, a1) : -INFINITY;
        #pragma unroll
        for (int o = 16; o; o >>= 1) m = fmaxf(m, __shfl_xor_sync(0xffffffffu, m, o));
        float ssum = (lane < 20) ? (expf(a0 - m) + expf(a1 - m)) : 0.f;
        #pragma unroll
        for (int o = 16; o; o >>= 1) ssum += __shfl_xor_sync(0xffffffffu, ssum, o);
        float lse = m + logf(ssum);

        if (lane < 20) {
            out[(size_t)node * 40 + lane]      = a0 - lse;
            out[(size_t)node * 40 + lane + 20] = a1 - lse;
        }
        __syncwarp();
    }
}

// ---------------- launch ----------------------------------------------------------
static cudaStream_t get_aux_stream() {
    static cudaStream_t s = [] {
        cudaStream_t t;
        cudaStreamCreateWithFlags(&t, cudaStreamNonBlocking);
        return t;
    }();
    return s;
}
static cudaEvent_t make_event() {
    cudaEvent_t e;
    cudaEventCreateWithFlags(&e, cudaEventDisableTiming);
    return e;
}
static cudaEvent_t get_ev_root() { static cudaEvent_t e = make_event(); return e; }
static cudaEvent_t get_ev_dinv() { static cudaEvent_t e = make_event(); return e; }
static cudaEvent_t get_ev_csr()  { static cudaEvent_t e = make_event(); return e; }

extern "C" void kernel_launch(void* const* d_in, const int* in_sizes, int n_in,
                              void* d_out, int out_size)
{
    const float* x  = (const float*)d_in[0];
    const char*  ei = (const char*) d_in[1];
    const float* W1 = (const float*)d_in[2];
    const float* b1 = (const float*)d_in[3];
    const float* W2 = (const float*)d_in[4];
    const float* b2 = (const float*)d_in[5];
    const float* Wf = (const float*)d_in[6];
    const float* bf = (const float*)d_in[7];
    float* out = (float*)d_out;

    const int n = in_sizes[0] / 128;
    const int E = in_sizes[1] / 2;

    __nv_bfloat162 *hbuf, *h2buf;
    int* cntbuf;
    cudaGetSymbolAddress((void**)&hbuf,  g_h);
    cudaGetSymbolAddress((void**)&h2buf, g_h2);
    cudaGetSymbolAddress((void**)&cntbuf, g_cnt);

    const int eb2     = (int)(((long long)E / 2 + 256) / 256);  // 2 edges/thread
    const int gemmb   = (n + 127) / 128;
    const int fuseb   = (n + 31) / 32;
    const int scanb   = (n + SCAN_B - 1) / SCAN_B;
    const int scaleb  = (n * 32 + 255) / 256;

    cudaStream_t aux = get_aux_stream();
    cudaEvent_t evRoot = get_ev_root();
    cudaEvent_t evDinv = get_ev_dinv();
    cudaEvent_t evCSR  = get_ev_csr();

    // fork aux stream off the captured (default) stream
    cudaEventRecord(evRoot, 0);
    cudaStreamWaitEvent(aux, evRoot, 0);

    // main: gemm1 overlaps the whole CSR build
    k_gemm1<<<gemmb, 256>>>(x, W1, hbuf, n);

    // aux: CSR build chain (compressed)
    cudaMemsetAsync(cntbuf, 0, (size_t)n * sizeof(int), aux);
    k_detect<<<1, 32, 0, aux>>>((const unsigned int*)ei);
    k_hist<<<eb2, 256, 0, aux>>>(ei, E);
    k_scan1<<<scanb, SCAN_B, 0, aux>>>(n);          // also computes dinv
    cudaEventRecord(evDinv, aux);
    k_scanfin<<<scanb, SCAN_B, 0, aux>>>(n, scanb);
    k_fill<<<eb2, 256, 0, aux>>>(ei, E);
    cudaEventRecord(evCSR, aux);

    // main: scale after dinv; gathers after CSR
    cudaStreamWaitEvent(0, evDinv, 0);
    k_scale<<<scaleb, 256>>>(hbuf, n);
    cudaStreamWaitEvent(0, evCSR, 0);

    k_gather_gemm<<<fuseb, 256>>>(hbuf, b1, W2, h2buf, n);
    k_gather_final<<<fuseb, 256>>>(h2buf, b2, Wf, bf, out, n);
}